// round 7
// baseline (speedup 1.0000x reference)
#include <cuda_runtime.h>
#include <cuda_fp16.h>
#include <cstdint>

#define IN_CH  512
#define HID    16
#define OUT_CH 64
#define MAX_NODES 100352
#define MAX_EDGES 3276800

// ---- scratch (device globals; no allocation allowed) ----
__device__ float  g_deg [MAX_NODES];
__device__ float  g_dinv[MAX_NODES];
__device__ __half g_h1h [MAX_NODES * HID];   // fp16 dinv-prescaled x@W1   (3.2 MB, L2-resident)
__device__ __half g_zh  [MAX_NODES * HID];   // fp16 dinv*relu(dinv*agg1+b1)
__device__ float  g_agg1[MAX_NODES * HID];
__device__ float  g_agg2[MAX_NODES * HID];

// vectorized f32 reduction (sm_90+): 1 request instead of 4 scalar atomics
__device__ __forceinline__ void red_add_v4(float* p, float4 v) {
    asm volatile("red.global.add.v4.f32 [%0], {%1,%2,%3,%4};"
                 :: "l"(p), "f"(v.x), "f"(v.y), "f"(v.z), "f"(v.w) : "memory");
}

// packed fp32x2 FMA (Blackwell FFMA2 — only reachable via PTX)
__device__ __forceinline__ void ffma2(unsigned long long& d, unsigned long long a,
                                      unsigned long long b) {
    asm("fma.rn.f32x2 %0, %1, %2, %0;" : "+l"(d) : "l"(a), "l"(b));
}

// ---------------------------------------------------------------- zero (agg1 + deg)
__global__ void zero_kernel(int n) {
    int i = blockIdx.x * blockDim.x + threadIdx.x;
    int t4 = n * HID / 4;
    if (i < t4) ((float4*)g_agg1)[i] = make_float4(0.f, 0.f, 0.f, 0.f);
    if (i < n) g_deg[i] = 0.f;
}

// ---------------------------------------------------------------- degree
__global__ void deg_kernel(const int* __restrict__ ei1, const float* __restrict__ w1, int E1,
                           const int* __restrict__ ei2, const float* __restrict__ w2, int E2) {
    int i = blockIdx.x * blockDim.x + threadIdx.x;
    if (i < E1) {
        atomicAdd(&g_deg[ei1[i]], w1[i]);
    } else {
        int j = i - E1;
        if (j < E2) atomicAdd(&g_deg[ei2[j]], w2[j]);
    }
}

__global__ void dinv_kernel(int n) {
    int i = blockIdx.x * blockDim.x + threadIdx.x;
    if (i >= n) return;
    float d = g_deg[i];
    g_dinv[i] = d > 0.f ? rsqrtf(fmaxf(d, 1e-12f)) : 0.f;
}

// ---------------------------------------------------------------- h1h = fp16( dinv .* (x @ W1) )
// lane-per-node. KCHUNK=16, XOR-swizzled x tile (no padding) -> smem 48KB ->
// 4 blocks/SM (8 warps/SMSP). x read as LDS.128 per 4k.
#define G1_WARPS   8
#define G1_THREADS (G1_WARPS * 32)
#define G1_KCHUNK  16
#define G1_SMEM_FLOATS (IN_CH * HID + G1_WARPS * 32 * G1_KCHUNK)

__global__ void __launch_bounds__(G1_THREADS, 4)
gemm1_kernel(const float* __restrict__ x, const float* __restrict__ W1, int n) {
    extern __shared__ float smem[];
    float* Ws = smem;  // [512][16] row-major, 32KB
    const int warp = threadIdx.x >> 5;
    const int lane = threadIdx.x & 31;
    float* xs = smem + IN_CH * HID + warp * (32 * G1_KCHUNK);

    for (int t = threadIdx.x; t < IN_CH * HID / 4; t += blockDim.x)
        ((float4*)Ws)[t] = ((const float4*)W1)[t];
    __syncthreads();

    const int nodebase = blockIdx.x * G1_THREADS + warp * 32;
    const int node = nodebase + lane;
    const int lswz = (lane >> 1) & 3;

    unsigned long long acc[8];
#pragma unroll
    for (int j = 0; j < 8; j++) acc[j] = 0ull;

    for (int kc = 0; kc < IN_CH; kc += G1_KCHUNK) {
        // stage 32 rows x 16 floats, float4 stores, XOR swizzle on float4 slot
#pragma unroll
        for (int t = 0; t < 4; t++) {
            int idx = t * 32 + lane;      // 0..127
            int r   = idx >> 2;           // row in tile
            int c   = idx & 3;            // float4 slot
            int nd  = nodebase + r;
            float4 v = make_float4(0.f, 0.f, 0.f, 0.f);
            if (nd < n) v = ((const float4*)x)[(size_t)nd * (IN_CH / 4) + (kc >> 2) + c];
            *(float4*)(xs + r * G1_KCHUNK + ((c ^ ((r >> 1) & 3)) << 2)) = v;
        }
        __syncwarp();
        const float* xrow = xs + lane * G1_KCHUNK;
#pragma unroll
        for (int k4 = 0; k4 < 4; k4++) {
            const float4 xq = *(const float4*)(xrow + ((k4 ^ lswz) << 2));
            const float xv4[4] = {xq.x, xq.y, xq.z, xq.w};
#pragma unroll
            for (int s = 0; s < 4; s++) {
                unsigned long long xx;
                asm("mov.b64 %0, {%1, %1};" : "=l"(xx) : "f"(xv4[s]));
                const ulonglong2* wr = (const ulonglong2*)(Ws + (kc + k4 * 4 + s) * HID);
                ulonglong2 w0 = wr[0], w1 = wr[1], w2 = wr[2], w3 = wr[3];
                ffma2(acc[0], w0.x, xx); ffma2(acc[1], w0.y, xx);
                ffma2(acc[2], w1.x, xx); ffma2(acc[3], w1.y, xx);
                ffma2(acc[4], w2.x, xx); ffma2(acc[5], w2.y, xx);
                ffma2(acc[6], w3.x, xx); ffma2(acc[7], w3.y, xx);
            }
        }
        __syncwarp();
    }

    if (node < n) {
        float dv = __ldg(g_dinv + node);
        float out[HID];
#pragma unroll
        for (int j = 0; j < 8; j++)
            asm("mov.b64 {%0, %1}, %2;" : "=f"(out[2*j]), "=f"(out[2*j+1]) : "l"(acc[j]));
        __half2 h[8];
#pragma unroll
        for (int j = 0; j < 8; j++)
            h[j] = __floats2half2_rn(out[2*j] * dv, out[2*j+1] * dv);
        uint4* o = (uint4*)(g_h1h + (size_t)node * HID);
        const unsigned* hu = (const unsigned*)h;
        o[0] = make_uint4(hu[0], hu[1], hu[2], hu[3]);
        o[1] = make_uint4(hu[4], hu[5], hu[6], hu[7]);
    }
}

// ---------------------------------------------------------------- scatter
// pair-per-edge: 2 consecutive lanes per edge, each gathers 8 fp16 channels
// (uint4 = 16B = 1 sector) and issues 2 red.v4 fp32. Gather tables are 3.2 MB
// fp16 -> L2-resident, half the gather traffic of fp32.
template <int LAYER>
__global__ void scatter_kernel(const int* __restrict__ ei1, const float* __restrict__ w1, int E1,
                               const int* __restrict__ ei2, const float* __restrict__ w2, int E2) {
    int t = blockIdx.x * blockDim.x + threadIdx.x;
    int e   = t >> 1;
    int sub = t & 1;
    int row, col;
    float w;
    if (e < E1) {
        row = __ldg(ei1 + e); col = __ldg(ei1 + E1 + e); w = __ldg(w1 + e);
    } else {
        int j = e - E1;
        if (j >= E2) return;
        row = __ldg(ei2 + j); col = __ldg(ei2 + E2 + j); w = __ldg(w2 + j);
    }

    const __half* src = (LAYER == 1) ? g_h1h : g_zh;
    float*        dst = (LAYER == 1) ? g_agg1 : g_agg2;

    uint4 hv = __ldg((const uint4*)(src + (size_t)col * HID + sub * 8));
    __half2 h0 = *(__half2*)&hv.x, h1 = *(__half2*)&hv.y;
    __half2 h2 = *(__half2*)&hv.z, h3 = *(__half2*)&hv.w;
    float2 f0 = __half22float2(h0), f1 = __half22float2(h1);
    float2 f2 = __half22float2(h2), f3 = __half22float2(h3);

    float* d = dst + (size_t)row * HID + sub * 8;
    red_add_v4(d + 0, make_float4(f0.x * w, f0.y * w, f1.x * w, f1.y * w));
    red_add_v4(d + 4, make_float4(f2.x * w, f2.y * w, f3.x * w, f3.y * w));
}

// ---------------------------------------------------------------- zh = fp16(dinv.*relu(dinv.*agg1 + b1)); zero agg2
__global__ void relu_kernel(const float* __restrict__ b1, int n) {
    int i = blockIdx.x * blockDim.x + threadIdx.x;   // float4 index
    int t4 = n * HID / 4;
    if (i >= t4) return;
    int node = i >> 2;
    float dv = __ldg(g_dinv + node);
    float4 b = __ldg(((const float4*)b1) + (i & 3));
    float4 v = ((float4*)g_agg1)[i];
    v.x = dv * fmaxf(dv * v.x + b.x, 0.f);
    v.y = dv * fmaxf(dv * v.y + b.y, 0.f);
    v.z = dv * fmaxf(dv * v.z + b.z, 0.f);
    v.w = dv * fmaxf(dv * v.w + b.w, 0.f);
    __half2 h0 = __floats2half2_rn(v.x, v.y);
    __half2 h1 = __floats2half2_rn(v.z, v.w);
    ((uint2*)g_zh)[i] = make_uint2(*(unsigned*)&h0, *(unsigned*)&h1);
    ((float4*)g_agg2)[i] = make_float4(0.f, 0.f, 0.f, 0.f);
}

// ---------------------------------------------------------------- out = log_softmax((dinv.*agg2) @ W2 + b2)
#define OUT_WARPS 8
__global__ void out_kernel(const float* __restrict__ W2, const float* __restrict__ b2,
                           float* __restrict__ out, int n) {
    __shared__ float W2s[HID * OUT_CH];
    for (int t = threadIdx.x; t < HID * OUT_CH / 4; t += blockDim.x)
        ((float4*)W2s)[t] = ((const float4*)W2)[t];
    __syncthreads();

    int warp = threadIdx.x >> 5, lane = threadIdx.x & 31;
    int node = blockIdx.x * OUT_WARPS + warp;
    if (node >= n) return;

    float dv = __ldg(g_dinv + node);
    const float4* a4 = (const float4*)(g_agg2 + (size_t)node * HID);
    float4 a0 = a4[0], a1 = a4[1], a2 = a4[2], a3 = a4[3];
    float a[16];
    a[0]  = a0.x; a[1]  = a0.y; a[2]  = a0.z; a[3]  = a0.w;
    a[4]  = a1.x; a[5]  = a1.y; a[6]  = a1.z; a[7]  = a1.w;
    a[8]  = a2.x; a[9]  = a2.y; a[10] = a2.z; a[11] = a2.w;
    a[12] = a3.x; a[13] = a3.y; a[14] = a3.z; a[15] = a3.w;
#pragma unroll
    for (int k = 0; k < HID; k++) a[k] *= dv;

    float acc0 = b2[lane];
    float acc1 = b2[lane + 32];
#pragma unroll
    for (int k = 0; k < HID; k++) {
        acc0 += a[k] * W2s[k * OUT_CH + lane];
        acc1 += a[k] * W2s[k * OUT_CH + lane + 32];
    }

    float m = fmaxf(acc0, acc1);
#pragma unroll
    for (int off = 16; off >= 1; off >>= 1)
        m = fmaxf(m, __shfl_xor_sync(0xffffffffu, m, off));
    float s = expf(acc0 - m) + expf(acc1 - m);
#pragma unroll
    for (int off = 16; off >= 1; off >>= 1)
        s += __shfl_xor_sync(0xffffffffu, s, off);
    float lse = m + logf(s);

    out[(size_t)node * OUT_CH + lane]      = acc0 - lse;
    out[(size_t)node * OUT_CH + lane + 32] = acc1 - lse;
}

// ---------------------------------------------------------------- launch
extern "C" void kernel_launch(void* const* d_in, const int* in_sizes, int n_in,
                              void* d_out, int out_size) {
    const float* x   = (const float*)d_in[0];
    const int*   ei1 = (const int*)  d_in[1];
    const float* ew1 = (const float*)d_in[2];
    const int*   ei2 = (const int*)  d_in[3];
    const float* ew2 = (const float*)d_in[4];
    const float* W1  = (const float*)d_in[5];
    const float* b1  = (const float*)d_in[6];
    const float* W2  = (const float*)d_in[7];
    const float* b2  = (const float*)d_in[8];
    float* out = (float*)d_out;

    int n  = in_sizes[0] / IN_CH;
    int E1 = in_sizes[2];
    int E2 = in_sizes[4];
    int Et = E1 + E2;

    const int G1_SMEM = G1_SMEM_FLOATS * (int)sizeof(float);
    cudaFuncSetAttribute(gemm1_kernel, cudaFuncAttributeMaxDynamicSharedMemorySize, G1_SMEM);

    zero_kernel<<<(n * HID / 4 + 255) / 256, 256>>>(n);
    deg_kernel<<<(Et + 255) / 256, 256>>>(ei1, ew1, E1, ei2, ew2, E2);
    dinv_kernel<<<(n + 255) / 256, 256>>>(n);
    gemm1_kernel<<<(n + G1_THREADS - 1) / G1_THREADS, G1_THREADS, G1_SMEM>>>(x, W1, n);
    scatter_kernel<1><<<(2 * Et + 255) / 256, 256>>>(ei1, ew1, E1, ei2, ew2, E2);
    relu_kernel<<<(n * HID / 4 + 255) / 256, 256>>>(b1, n);
    scatter_kernel<2><<<(2 * Et + 255) / 256, 256>>>(ei1, ew1, E1, ei2, ew2, E2);
    out_kernel<<<(n + OUT_WARPS - 1) / OUT_WARPS, OUT_WARPS * 32>>>(W2, b2, out, n);
}

// round 8
// speedup vs baseline: 1.1673x; 1.1673x over previous
#include <cuda_runtime.h>
#include <cstdint>

#define IN_CH  512
#define HID    16
#define OUT_CH 64
#define MAX_NODES 100352
#define MAX_EDGES 3276800

// ---- scratch (device globals; no allocation allowed) ----
__device__ float g_deg [MAX_NODES];
__device__ float g_dinv[MAX_NODES];
__device__ float g_h1  [MAX_NODES * HID];   // dinv-prescaled x@W1
__device__ float g_agg1[MAX_NODES * HID];
__device__ float g_agg2[MAX_NODES * HID];

// vectorized f32 reduction (sm_90+): 1 request instead of 4 scalar atomics
__device__ __forceinline__ void red_add_v4(float* p, float4 v) {
    asm volatile("red.global.add.v4.f32 [%0], {%1,%2,%3,%4};"
                 :: "l"(p), "f"(v.x), "f"(v.y), "f"(v.z), "f"(v.w) : "memory");
}

// packed fp32x2 FMA (Blackwell FFMA2 — only reachable via PTX)
__device__ __forceinline__ void ffma2(unsigned long long& d, unsigned long long a,
                                      unsigned long long b) {
    asm("fma.rn.f32x2 %0, %1, %2, %0;" : "+l"(d) : "l"(a), "l"(b));
}

__device__ __forceinline__ void cp_async16(uint32_t dst, const void* src) {
    asm volatile("cp.async.cg.shared.global [%0], [%1], 16;" :: "r"(dst), "l"(src));
}

// ---------------------------------------------------------------- zero (agg1 + deg)
__global__ void zero_kernel(int n) {
    int i = blockIdx.x * blockDim.x + threadIdx.x;
    int t4 = n * HID / 4;
    if (i < t4) ((float4*)g_agg1)[i] = make_float4(0.f, 0.f, 0.f, 0.f);
    if (i < n) g_deg[i] = 0.f;
}

// ---------------------------------------------------------------- degree
__global__ void deg_kernel(const int* __restrict__ ei1, const float* __restrict__ w1, int E1,
                           const int* __restrict__ ei2, const float* __restrict__ w2, int E2) {
    int i = blockIdx.x * blockDim.x + threadIdx.x;
    if (i < E1) {
        atomicAdd(&g_deg[ei1[i]], w1[i]);
    } else {
        int j = i - E1;
        if (j < E2) atomicAdd(&g_deg[ei2[j]], w2[j]);
    }
}

__global__ void dinv_kernel(int n) {
    int i = blockIdx.x * blockDim.x + threadIdx.x;
    if (i >= n) return;
    float d = g_deg[i];
    g_dinv[i] = d > 0.f ? rsqrtf(fmaxf(d, 1e-12f)) : 0.f;
}

// ---------------------------------------------------------------- h1 = dinv .* (x @ W1)
// lane-per-node, KCHUNK=16 XOR-swizzled tile, cp.async double-buffered:
// prefetch chunk c+1 while computing chunk c -> hides LDG latency that
// previously left issue at 37%.
#define G1_WARPS   8
#define G1_THREADS (G1_WARPS * 32)
#define G1_KCHUNK  16
#define G1_BUF_FLOATS (32 * G1_KCHUNK)                 // 512 floats per buffer
#define G1_SMEM_FLOATS (IN_CH * HID + G1_WARPS * 2 * G1_BUF_FLOATS)  // 64KB

__global__ void __launch_bounds__(G1_THREADS, 3)
gemm1_kernel(const float* __restrict__ x, const float* __restrict__ W1, int n) {
    extern __shared__ float smem[];
    float* Ws = smem;  // [512][16] row-major, 32KB
    const int warp = threadIdx.x >> 5;
    const int lane = threadIdx.x & 31;
    float* xb = smem + IN_CH * HID + warp * (2 * G1_BUF_FLOATS);
    const uint32_t xb_s = (uint32_t)__cvta_generic_to_shared(xb);

    for (int t = threadIdx.x; t < IN_CH * HID / 4; t += blockDim.x)
        ((float4*)Ws)[t] = ((const float4*)W1)[t];
    __syncthreads();

    const int nodebase = blockIdx.x * G1_THREADS + warp * 32;
    const int node = nodebase + lane;
    const int lswz = (lane >> 1) & 3;

    // per-lane staging coordinates (4 cp.async of 16B per chunk)
    int st_r[4], st_c[4];
    const float4* st_src[4];
#pragma unroll
    for (int t = 0; t < 4; t++) {
        int idx = t * 32 + lane;           // 0..127
        st_r[t] = idx >> 2;
        st_c[t] = idx & 3;
        int nd = nodebase + st_r[t];
        // OOB nodes stage row 0 (values discarded at the store guard)
        st_src[t] = (const float4*)x + ((nd < n) ? (size_t)nd * (IN_CH / 4) : 0) + st_c[t];
    }

    unsigned long long acc[8];
#pragma unroll
    for (int j = 0; j < 8; j++) acc[j] = 0ull;

    // prefetch chunk 0 into buffer 0
#pragma unroll
    for (int t = 0; t < 4; t++) {
        uint32_t dst = xb_s + 4u * (st_r[t] * G1_KCHUNK +
                                    ((st_c[t] ^ ((st_r[t] >> 1) & 3)) << 2));
        cp_async16(dst, st_src[t]);
    }
    asm volatile("cp.async.commit_group;" ::: "memory");

#pragma unroll 2
    for (int c = 0; c < IN_CH / G1_KCHUNK; c++) {
        const int kc = c * G1_KCHUNK;
        const int cur = c & 1;
        if (c + 1 < IN_CH / G1_KCHUNK) {
            const int nb = (c + 1) & 1;
            const int nk4 = (kc + G1_KCHUNK) >> 2;
#pragma unroll
            for (int t = 0; t < 4; t++) {
                uint32_t dst = xb_s + 4u * (nb * G1_BUF_FLOATS + st_r[t] * G1_KCHUNK +
                                            ((st_c[t] ^ ((st_r[t] >> 1) & 3)) << 2));
                cp_async16(dst, st_src[t] + nk4);
            }
            asm volatile("cp.async.commit_group;" ::: "memory");
            asm volatile("cp.async.wait_group 1;" ::: "memory");
        } else {
            asm volatile("cp.async.wait_group 0;" ::: "memory");
        }
        __syncwarp();

        const float* xrow = xb + cur * G1_BUF_FLOATS + lane * G1_KCHUNK;
#pragma unroll
        for (int k4 = 0; k4 < 4; k4++) {
            const float4 xq = *(const float4*)(xrow + ((k4 ^ lswz) << 2));
            const float xv4[4] = {xq.x, xq.y, xq.z, xq.w};
#pragma unroll
            for (int s = 0; s < 4; s++) {
                unsigned long long xx;
                asm("mov.b64 %0, {%1, %1};" : "=l"(xx) : "f"(xv4[s]));
                const ulonglong2* wr = (const ulonglong2*)(Ws + (kc + k4 * 4 + s) * HID);
                ulonglong2 w0 = wr[0], w1 = wr[1], w2 = wr[2], w3 = wr[3];
                ffma2(acc[0], w0.x, xx); ffma2(acc[1], w0.y, xx);
                ffma2(acc[2], w1.x, xx); ffma2(acc[3], w1.y, xx);
                ffma2(acc[4], w2.x, xx); ffma2(acc[5], w2.y, xx);
                ffma2(acc[6], w3.x, xx); ffma2(acc[7], w3.y, xx);
            }
        }
        __syncwarp();
    }

    if (node < n) {
        float dv = __ldg(g_dinv + node);
        float out[HID];
#pragma unroll
        for (int j = 0; j < 8; j++)
            asm("mov.b64 {%0, %1}, %2;" : "=f"(out[2*j]), "=f"(out[2*j+1]) : "l"(acc[j]));
#pragma unroll
        for (int j = 0; j < HID; j++) out[j] *= dv;
        float4* o = (float4*)(g_h1 + (size_t)node * HID);
        o[0] = make_float4(out[0],  out[1],  out[2],  out[3]);
        o[1] = make_float4(out[4],  out[5],  out[6],  out[7]);
        o[2] = make_float4(out[8],  out[9],  out[10], out[11]);
        o[3] = make_float4(out[12], out[13], out[14], out[15]);
    }
}

// ---------------------------------------------------------------- scatter
// quad-per-edge fp32 (R6 winner): 4 consecutive lanes per edge, float4 each.
template <int LAYER>
__global__ void scatter_kernel(const int* __restrict__ ei1, const float* __restrict__ w1, int E1,
                               const int* __restrict__ ei2, const float* __restrict__ w2, int E2) {
    int t = blockIdx.x * blockDim.x + threadIdx.x;
    int e   = t >> 2;
    int sub = t & 3;
    int row, col;
    float w;
    if (e < E1) {
        row = __ldg(ei1 + e); col = __ldg(ei1 + E1 + e); w = __ldg(w1 + e);
    } else {
        int j = e - E1;
        if (j >= E2) return;
        row = __ldg(ei2 + j); col = __ldg(ei2 + E2 + j); w = __ldg(w2 + j);
    }

    const float* src = (LAYER == 1) ? g_h1 : g_agg1;
    float*       dst = (LAYER == 1) ? g_agg1 : g_agg2;

    float4 v = __ldg(((const float4*)(src + (size_t)col * HID)) + sub);
    v.x *= w; v.y *= w; v.z *= w; v.w *= w;
    red_add_v4(dst + (size_t)row * HID + sub * 4, v);
}

// ---------------------------------------------------------------- agg1 = dinv.*relu(dinv.*agg1 + b1); zero agg2
__global__ void relu_kernel(const float* __restrict__ b1, int n) {
    int i = blockIdx.x * blockDim.x + threadIdx.x;   // float4 index
    int t4 = n * HID / 4;
    if (i >= t4) return;
    int node = i >> 2;
    float dv = __ldg(g_dinv + node);
    float4 b = __ldg(((const float4*)b1) + (i & 3));
    float4 v = ((float4*)g_agg1)[i];
    v.x = dv * fmaxf(dv * v.x + b.x, 0.f);
    v.y = dv * fmaxf(dv * v.y + b.y, 0.f);
    v.z = dv * fmaxf(dv * v.z + b.z, 0.f);
    v.w = dv * fmaxf(dv * v.w + b.w, 0.f);
    ((float4*)g_agg1)[i] = v;
    ((float4*)g_agg2)[i] = make_float4(0.f, 0.f, 0.f, 0.f);
}

// ---------------------------------------------------------------- out = log_softmax((dinv.*agg2) @ W2 + b2)
#define OUT_WARPS 8
__global__ void out_kernel(const float* __restrict__ W2, const float* __restrict__ b2,
                           float* __restrict__ out, int n) {
    __shared__ float W2s[HID * OUT_CH];
    for (int t = threadIdx.x; t < HID * OUT_CH / 4; t += blockDim.x)
        ((float4*)W2s)[t] = ((const float4*)W2)[t];
    __syncthreads();

    int warp = threadIdx.x >> 5, lane = threadIdx.x & 31;
    int node = blockIdx.x * OUT_WARPS + warp;
    if (node >= n) return;

    float dv = __ldg(g_dinv + node);
    const float4* a4 = (const float4*)(g_agg2 + (size_t)node * HID);
    float4 a0 = a4[0], a1 = a4[1], a2 = a4[2], a3 = a4[3];
    float a[16];
    a[0]  = a0.x; a[1]  = a0.y; a[2]  = a0.z; a[3]  = a0.w;
    a[4]  = a1.x; a[5]  = a1.y; a[6]  = a1.z; a[7]  = a1.w;
    a[8]  = a2.x; a[9]  = a2.y; a[10] = a2.z; a[11] = a2.w;
    a[12] = a3.x; a[13] = a3.y; a[14] = a3.z; a[15] = a3.w;
#pragma unroll
    for (int k = 0; k < HID; k++) a[k] *= dv;

    float acc0 = b2[lane];
    float acc1 = b2[lane + 32];
#pragma unroll
    for (int k = 0; k < HID; k++) {
        acc0 += a[k] * W2s[k * OUT_CH + lane];
        acc1 += a[k] * W2s[k * OUT_CH + lane + 32];
    }

    float m = fmaxf(acc0, acc1);
#pragma unroll
    for (int off = 16; off >= 1; off >>= 1)
        m = fmaxf(m, __shfl_xor_sync(0xffffffffu, m, off));
    float s = expf(acc0 - m) + expf(acc1 - m);
#pragma unroll
    for (int off = 16; off >= 1; off >>= 1)
        s += __shfl_xor_sync(0xffffffffu, s, off);
    float lse = m + logf(s);

    out[(size_t)node * OUT_CH + lane]      = acc0 - lse;
    out[(size_t)node * OUT_CH + lane + 32] = acc1 - lse;
}

// ---------------------------------------------------------------- launch
extern "C" void kernel_launch(void* const* d_in, const int* in_sizes, int n_in,
                              void* d_out, int out_size) {
    const float* x   = (const float*)d_in[0];
    const int*   ei1 = (const int*)  d_in[1];
    const float* ew1 = (const float*)d_in[2];
    const int*   ei2 = (const int*)  d_in[3];
    const float* ew2 = (const float*)d_in[4];
    const float* W1  = (const float*)d_in[5];
    const float* b1  = (const float*)d_in[6];
    const float* W2  = (const float*)d_in[7];
    const float* b2  = (const float*)d_in[8];
    float* out = (float*)d_out;

    int n  = in_sizes[0] / IN_CH;
    int E1 = in_sizes[2];
    int E2 = in_sizes[4];
    int Et = E1 + E2;

    const int G1_SMEM = G1_SMEM_FLOATS * (int)sizeof(float);
    cudaFuncSetAttribute(gemm1_kernel, cudaFuncAttributeMaxDynamicSharedMemorySize, G1_SMEM);

    zero_kernel<<<(n * HID / 4 + 255) / 256, 256>>>(n);
    deg_kernel<<<(Et + 255) / 256, 256>>>(ei1, ew1, E1, ei2, ew2, E2);
    dinv_kernel<<<(n + 255) / 256, 256>>>(n);
    gemm1_kernel<<<(n + G1_THREADS - 1) / G1_THREADS, G1_THREADS, G1_SMEM>>>(x, W1, n);
    scatter_kernel<1><<<(4 * Et + 255) / 256, 256>>>(ei1, ew1, E1, ei2, ew2, E2);
    relu_kernel<<<(n * HID / 4 + 255) / 256, 256>>>(b1, n);
    scatter_kernel<2><<<(4 * Et + 255) / 256, 256>>>(ei1, ew1, E1, ei2, ew2, E2);
    out_kernel<<<(n + OUT_WARPS - 1) / OUT_WARPS, OUT_WARPS * 32>>>(W2, b2, out, n);
}